// round 12
// baseline (speedup 1.0000x reference)
#include <cuda_runtime.h>
#include <cstdint>
#include <cstddef>

#define B_ 512
#define N_ 50
#define D_ 256
#define STEP_ 3

// shared-memory layout (float offsets)
#define SM_H      0        // [50][256] hidden
#define SM_HN     12800    // [50][256] noise slab (steps) / h0 buffer (gating)
#define SM_EM     25600    // [50][50] attention matrix
#define SM_STAR   28100    // [256]
#define SM_SIMB   28356    // [64]
#define SM_GMF    28420    // [64]
#define SM_NID    28484    // [64]
#define SM_FLOATS 28548
#define SMEM_BYTES (SM_FLOATS * 4)

// global scratch for hg accumulation (sum of step embeddings)
__device__ float g_hg[(size_t)B_ * N_ * D_];

// ---------------- helpers ----------------
__device__ __forceinline__ float wsum(float v) {
#pragma unroll
    for (int o = 16; o; o >>= 1) v += __shfl_xor_sync(0xffffffffu, v, o);
    return v;
}
__device__ __forceinline__ float sx(float v, int o) {
    return __shfl_xor_sync(0xffffffffu, v, o);
}
__device__ __forceinline__ float sgnf(float x) {
    return x > 0.f ? 1.f : (x < 0.f ? -1.f : 0.f);
}
__device__ __forceinline__ float dot4(float4 a, float4 b) {
    return a.x * b.x + a.y * b.y + a.z * b.z + a.w * b.w;
}
__device__ __forceinline__ float4 fma4(float p, float4 y, float4 a) {
    a.x = fmaf(p, y.x, a.x); a.y = fmaf(p, y.y, a.y);
    a.z = fmaf(p, y.z, a.z); a.w = fmaf(p, y.w, a.w);
    return a;
}
__device__ __forceinline__ float4 mul4(float4 a, float4 b) {
    return make_float4(a.x * b.x, a.y * b.y, a.z * b.z, a.w * b.w);
}
// packed f32x2 (FFMA2) — only reachable via PTX
__device__ __forceinline__ unsigned long long pk2(float lo, float hi) {
    unsigned long long r;
    asm("mov.b64 %0, {%1, %2};" : "=l"(r) : "f"(lo), "f"(hi));
    return r;
}
__device__ __forceinline__ void fma2(unsigned long long& d, unsigned long long a,
                                     unsigned long long b) {
    asm("fma.rn.f32x2 %0, %1, %2, %0;" : "+l"(d) : "l"(a), "l"(b));
}
__device__ __forceinline__ void up2(unsigned long long v, float& lo, float& hi) {
    asm("mov.b64 {%0, %1}, %2;" : "=f"(lo), "=f"(hi) : "l"(v));
}
__device__ __forceinline__ void cp16(uint32_t saddr, const void* gaddr) {
    asm volatile("cp.async.cg.shared.global [%0], [%1], 16;"
                 :: "r"(saddr), "l"(gaddr));
}

// dot of (hA,hB)∘(y0,y1) with a-vector #av (av is warp-uniform, 1..4)
__device__ __forceinline__ float pdot(float4 hA, float4 hB, float4 y0, float4 y1,
                                      const float4 aR[4][2], int av) {
    float4 t0 = mul4(hA, y0), t1 = mul4(hB, y1);
    float4 c0, c1;
    switch (av) {
        case 1:  c0 = aR[0][0]; c1 = aR[0][1]; break;
        case 2:  c0 = aR[1][0]; c1 = aR[1][1]; break;
        case 3:  c0 = aR[2][0]; c1 = aR[2][1]; break;
        default: c0 = aR[3][0]; c1 = aR[3][1]; break;
    }
    return dot4(t0, c0) + dot4(t1, c1);
}

// one GEMV segment: acc[n] += z[rbase+n][k0..k0+3] * W[k0..k0+3][o]
template <int NR>
__device__ __forceinline__ void gate_seg(unsigned long long* acc,
                                         const float* zbase, int rbase,
                                         const float* __restrict__ Wcol) {
    for (int kp = 0; kp < 64; kp++) {
        const int k0 = 4 * kp;
        float w0 = __ldg(Wcol + (k0 + 0) * D_);
        float w1 = __ldg(Wcol + (k0 + 1) * D_);
        float w2 = __ldg(Wcol + (k0 + 2) * D_);
        float w3 = __ldg(Wcol + (k0 + 3) * D_);
        unsigned long long wA = pk2(w0, w1), wB = pk2(w2, w3);
#pragma unroll
        for (int n = 0; n < NR; n++) {
            const ulonglong2 z =
                *(const ulonglong2*)(zbase + (rbase + n) * D_ + k0);
            fma2(acc[n], z.x, wA);
            fma2(acc[n], z.y, wB);
        }
    }
}

// gate A chunk: out0 = g*h0 + (1-g)*hL ; out1 partial = g*h0
template <int NR>
__device__ void gate_chunk_A(int rbase, const float* hN, const float* h,
                             const float* __restrict__ Whn, float bA,
                             float* out0, float* out1, size_t bo, int o) {
    unsigned long long acc[NR];
#pragma unroll
    for (int n = 0; n < NR; n++) acc[n] = 0ull;
    gate_seg<NR>(acc, hN, rbase, Whn + o);             // h0 vs W rows [0,256)
    gate_seg<NR>(acc, h,  rbase, Whn + D_ * D_ + o);   // hL vs W rows [256,512)
#pragma unroll
    for (int n = 0; n < NR; n++) {
        float lo, hi;
        up2(acc[n], lo, hi);
        float g = 1.f / (1.f + __expf(-(lo + hi + bA)));
        int row = rbase + n;
        float h0v = hN[row * D_ + o];
        float hLv = h[row * D_ + o];
        out0[bo + row * D_ + o] = g * h0v + (1.f - g) * hLv;
        out1[bo + row * D_ + o] = g * h0v;  // partial (alpha term)
    }
}

// gate B chunk: out1 += (1-g1)*hg1  (hg1 pre-staged in h buffer)
template <int NR>
__device__ void gate_chunk_B(int rbase, const float* hN, const float* h,
                             const float* __restrict__ Whn1, float bB,
                             float* out1, size_t bo, int o) {
    unsigned long long acc[NR];
#pragma unroll
    for (int n = 0; n < NR; n++) acc[n] = 0ull;
    gate_seg<NR>(acc, hN, rbase, Whn1 + o);            // h0 vs W1 rows [0,256)
    gate_seg<NR>(acc, h,  rbase, Whn1 + D_ * D_ + o);  // hg1 vs W1 rows [256,512)
#pragma unroll
    for (int n = 0; n < NR; n++) {
        float lo, hi;
        up2(acc[n], lo, hi);
        float g1 = 1.f / (1.f + __expf(-(lo + hi + bB)));
        int row = rbase + n;
        out1[bo + row * D_ + o] += (1.f - g1) * h[row * D_ + o];
    }
}

// ---------------- fused kernel: one block per batch element ----------------
__global__ void __launch_bounds__(256, 2) sg_kernel(
    const int* __restrict__ inputs, const int* __restrict__ Am,
    const int* __restrict__ gmask, const float* __restrict__ noise,
    const float* __restrict__ emb,
    const float* __restrict__ a0, const float* __restrict__ a1,
    const float* __restrict__ a2, const float* __restrict__ a3,
    const float* __restrict__ Whn, const float* __restrict__ bhn,
    const float* __restrict__ Whn1, const float* __restrict__ bhn1,
    float* __restrict__ out0, float* __restrict__ ostar, float* __restrict__ out1)
{
    extern __shared__ float sm[];
    float* h    = sm + SM_H;
    float* hN   = sm + SM_HN;   // noise slab during steps, h0 in gating
    float* eM   = sm + SM_EM;
    float* star = sm + SM_STAR;
    float* simb = sm + SM_SIMB;
    float* gmF  = sm + SM_GMF;
    int*   nid  = (int*)(sm + SM_NID);

    const int b = blockIdx.x;
    const int tid = threadIdx.x;
    const int lane = tid & 31;
    const int w = tid >> 5;
    const size_t bo = (size_t)b * N_ * D_;

    // ---- indices / mask ----
    if (tid < N_) {
        nid[tid] = inputs[b * N_ + tid];
        gmF[tid] = (float)gmask[b * N_ + tid];
    }
    __syncthreads();

    // ---- gather h0 ----
    for (int idx = tid; idx < N_ * D_; idx += 256) {
        int n = idx >> 8;
        h[idx] = emb[(size_t)nid[n] * D_ + (idx & 255)];
    }
    __syncthreads();

    // ---- initial star = ave_pool(h0, gm) ----
    {
        float s = 0.f, len = 0.f;
        for (int n = 0; n < N_; n++) {
            float g = gmF[n];
            s = fmaf(h[n * D_ + tid], g, s);
            len += g;
        }
        star[tid] = s / len;
    }
    __syncthreads();

    const uint32_t hN_s = (uint32_t)__cvta_generic_to_shared(hN);

    // ================= STEP loop =================
    for (int st = 0; st < STEP_; st++) {
        // ---- prefetch this step's noise slab into hN (overlaps e+agg) ----
        {
            const float* gsrc = noise + ((size_t)st * B_ + b) * N_ * D_;
            for (int c = tid; c < N_ * D_ / 4; c += 256)
                cp16(hN_s + c * 16, gsrc + c * 4);
            asm volatile("cp.async.commit_group;" ::: "memory");
        }

        // a-vectors to registers for this step's e-phase (L1-hit reloads)
        float4 aR[4][2];
        aR[0][0] = __ldg((const float4*)a0 + 2 * lane);
        aR[0][1] = __ldg((const float4*)a0 + 2 * lane + 1);
        aR[1][0] = __ldg((const float4*)a1 + 2 * lane);
        aR[1][1] = __ldg((const float4*)a1 + 2 * lane + 1);
        aR[2][0] = __ldg((const float4*)a2 + 2 * lane);
        aR[2][1] = __ldg((const float4*)a2 + 2 * lane + 1);
        aR[3][0] = __ldg((const float4*)a3 + 2 * lane);
        aR[3][1] = __ldg((const float4*)a3 + 2 * lane + 1);

        // ---- e-scores + softmax: one warp per ROW PAIR (ip, ip+25) ----
        for (int ip = w; ip < 25; ip += 8) {
            const int i0 = ip, i1 = ip + 25;
            const float4* hiA = (const float4*)(h + i0 * D_);
            const float4* hiB = (const float4*)(h + i1 * D_);
            const float4 h00 = hiA[2 * lane], h01 = hiA[2 * lane + 1];
            const float4 h10 = hiB[2 * lane], h11 = hiB[2 * lane + 1];

            const int* Ar0 = Am + (size_t)b * N_ * N_ + i0 * N_;
            const int* Ar1 = Am + (size_t)b * N_ * N_ + i1 * N_;
            float* er0 = eM + i0 * N_;
            float* er1 = eM + i1 * N_;

            // 12 groups of 4 j's × 2 rows = 8 dots; hj loaded ONCE per j
            for (int jb = 0; jb < 48; jb += 4) {
                const int2 cA = *(const int2*)(Ar0 + jb);
                const int2 cB = *(const int2*)(Ar0 + jb + 2);
                const int2 dA = *(const int2*)(Ar1 + jb);
                const int2 dB = *(const int2*)(Ar1 + jb + 2);
                float p0 = 0.f, p1 = 0.f, p2 = 0.f, p3 = 0.f;
                float p4 = 0.f, p5 = 0.f, p6 = 0.f, p7 = 0.f;
                if (cA.x | dA.x) {
                    const float4* y4 = (const float4*)(h + (jb + 0) * D_);
                    float4 y0 = y4[2 * lane], y1 = y4[2 * lane + 1];
                    if (cA.x) p0 = pdot(h00, h01, y0, y1, aR, cA.x);
                    if (dA.x) p4 = pdot(h10, h11, y0, y1, aR, dA.x);
                }
                if (cA.y | dA.y) {
                    const float4* y4 = (const float4*)(h + (jb + 1) * D_);
                    float4 y0 = y4[2 * lane], y1 = y4[2 * lane + 1];
                    if (cA.y) p1 = pdot(h00, h01, y0, y1, aR, cA.y);
                    if (dA.y) p5 = pdot(h10, h11, y0, y1, aR, dA.y);
                }
                if (cB.x | dB.x) {
                    const float4* y4 = (const float4*)(h + (jb + 2) * D_);
                    float4 y0 = y4[2 * lane], y1 = y4[2 * lane + 1];
                    if (cB.x) p2 = pdot(h00, h01, y0, y1, aR, cB.x);
                    if (dB.x) p6 = pdot(h10, h11, y0, y1, aR, dB.x);
                }
                if (cB.y | dB.y) {
                    const float4* y4 = (const float4*)(h + (jb + 3) * D_);
                    float4 y0 = y4[2 * lane], y1 = y4[2 * lane + 1];
                    if (cB.y) p3 = pdot(h00, h01, y0, y1, aR, cB.y);
                    if (dB.y) p7 = pdot(h10, h11, y0, y1, aR, dB.y);
                }
                // merged 8-value reduction: 16 SHFL total
                p0 += sx(p0, 16); p1 += sx(p1, 16); p2 += sx(p2, 16); p3 += sx(p3, 16);
                p4 += sx(p4, 16); p5 += sx(p5, 16); p6 += sx(p6, 16); p7 += sx(p7, 16);
                float m0 = (lane & 16) ? p1 : p0;
                float m1 = (lane & 16) ? p3 : p2;
                float m2 = (lane & 16) ? p5 : p4;
                float m3 = (lane & 16) ? p7 : p6;
                m0 += sx(m0, 8); m1 += sx(m1, 8); m2 += sx(m2, 8); m3 += sx(m3, 8);
                float n0 = (lane & 8) ? m1 : m0;
                float n1 = (lane & 8) ? m3 : m2;
                n0 += sx(n0, 4); n1 += sx(n1, 4);
                float r = (lane & 4) ? n1 : n0;
                r += sx(r, 2); r += sx(r, 1);
                // lane 4g holds value k = bitrev3(g); k<4 -> row0 j=jb+k, else row1
                if ((lane & 3) == 0) {
                    const int g = lane >> 2;
                    const int k = ((g & 1) << 2) | (g & 2) | (g >> 2);
                    int avv; float* dst;
                    switch (k) {
                        case 0:  avv = cA.x; dst = er0 + jb + 0; break;
                        case 1:  avv = cA.y; dst = er0 + jb + 1; break;
                        case 2:  avv = cB.x; dst = er0 + jb + 2; break;
                        case 3:  avv = cB.y; dst = er0 + jb + 3; break;
                        case 4:  avv = dA.x; dst = er1 + jb + 0; break;
                        case 5:  avv = dA.y; dst = er1 + jb + 1; break;
                        case 6:  avv = dB.x; dst = er1 + jb + 2; break;
                        default: avv = dB.y; dst = er1 + jb + 3; break;
                    }
                    *dst = avv ? (r > 0.f ? r : 0.2f * r) : -9e15f;
                }
            }
            {   // tail j = 48, 49 for both rows
                const int2 c = *(const int2*)(Ar0 + 48);
                const int2 d = *(const int2*)(Ar1 + 48);
                float q0 = 0.f, q1 = 0.f, q2 = 0.f, q3 = 0.f;
                if (c.x | d.x) {
                    const float4* y4 = (const float4*)(h + 48 * D_);
                    float4 y0 = y4[2 * lane], y1 = y4[2 * lane + 1];
                    if (c.x) q0 = pdot(h00, h01, y0, y1, aR, c.x);
                    if (d.x) q2 = pdot(h10, h11, y0, y1, aR, d.x);
                }
                if (c.y | d.y) {
                    const float4* y4 = (const float4*)(h + 49 * D_);
                    float4 y0 = y4[2 * lane], y1 = y4[2 * lane + 1];
                    if (c.y) q1 = pdot(h00, h01, y0, y1, aR, c.y);
                    if (d.y) q3 = pdot(h10, h11, y0, y1, aR, d.y);
                }
#pragma unroll
                for (int o = 16; o; o >>= 1) {
                    q0 += sx(q0, o);
                    q1 += sx(q1, o);
                    q2 += sx(q2, o);
                    q3 += sx(q3, o);
                }
                if (lane == 0) {
                    er0[48] = c.x ? (q0 > 0.f ? q0 : 0.2f * q0) : -9e15f;
                    er0[49] = c.y ? (q1 > 0.f ? q1 : 0.2f * q1) : -9e15f;
                    er1[48] = d.x ? (q2 > 0.f ? q2 : 0.2f * q2) : -9e15f;
                    er1[49] = d.y ? (q3 > 0.f ? q3 : 0.2f * q3) : -9e15f;
                }
            }
            __syncwarp();
            // in-place row softmax for both rows
#pragma unroll
            for (int rr = 0; rr < 2; rr++) {
                float* er = rr ? er1 : er0;
                float e1 = er[lane];
                float e2 = (lane < 18) ? er[32 + lane] : -3.0e38f;
                float m = fmaxf(e1, e2);
#pragma unroll
                for (int o = 16; o; o >>= 1)
                    m = fmaxf(m, __shfl_xor_sync(0xffffffffu, m, o));
                float q1 = __expf(e1 - m);
                float q2 = (lane < 18) ? __expf(e2 - m) : 0.f;
                float S = wsum(q1 + q2);
                float inv = 1.f / S;
                er[lane] = q1 * inv;
                if (lane < 18) er[32 + lane] = q2 * inv;
            }
        }
        __syncthreads();

        // ---- aggregation into registers: rows r = w + 8q, j unrolled x2 ----
        float4 acc[7][2];
#pragma unroll
        for (int q = 0; q < 7; q++) {
            acc[q][0] = make_float4(0, 0, 0, 0);
            acc[q][1] = make_float4(0, 0, 0, 0);
        }
        {
            const float* e0 = eM + (w + 0) * N_;
            const float* e1 = eM + (w + 8) * N_;
            const float* e2 = eM + (w + 16) * N_;
            const float* e3 = eM + (w + 24) * N_;
            const float* e4 = eM + (w + 32) * N_;
            const float* e5 = eM + (w + 40) * N_;
            const float* e6 = (w + 48 < N_) ? eM + (w + 48) * N_ : e0;
            const bool has6 = (w + 48 < N_);
            for (int j = 0; j < N_; j += 2) {
                const float4* ya = (const float4*)(h + j * D_);
                const float4* yb = (const float4*)(h + (j + 1) * D_);
                float4 ya0 = ya[2 * lane], ya1 = ya[2 * lane + 1];
                float4 yb0 = yb[2 * lane], yb1 = yb[2 * lane + 1];
                float2 pe;
                pe = *(const float2*)(e0 + j);
                acc[0][0] = fma4(pe.x, ya0, acc[0][0]); acc[0][1] = fma4(pe.x, ya1, acc[0][1]);
                acc[0][0] = fma4(pe.y, yb0, acc[0][0]); acc[0][1] = fma4(pe.y, yb1, acc[0][1]);
                pe = *(const float2*)(e1 + j);
                acc[1][0] = fma4(pe.x, ya0, acc[1][0]); acc[1][1] = fma4(pe.x, ya1, acc[1][1]);
                acc[1][0] = fma4(pe.y, yb0, acc[1][0]); acc[1][1] = fma4(pe.y, yb1, acc[1][1]);
                pe = *(const float2*)(e2 + j);
                acc[2][0] = fma4(pe.x, ya0, acc[2][0]); acc[2][1] = fma4(pe.x, ya1, acc[2][1]);
                acc[2][0] = fma4(pe.y, yb0, acc[2][0]); acc[2][1] = fma4(pe.y, yb1, acc[2][1]);
                pe = *(const float2*)(e3 + j);
                acc[3][0] = fma4(pe.x, ya0, acc[3][0]); acc[3][1] = fma4(pe.x, ya1, acc[3][1]);
                acc[3][0] = fma4(pe.y, yb0, acc[3][0]); acc[3][1] = fma4(pe.y, yb1, acc[3][1]);
                pe = *(const float2*)(e4 + j);
                acc[4][0] = fma4(pe.x, ya0, acc[4][0]); acc[4][1] = fma4(pe.x, ya1, acc[4][1]);
                acc[4][0] = fma4(pe.y, yb0, acc[4][0]); acc[4][1] = fma4(pe.y, yb1, acc[4][1]);
                pe = *(const float2*)(e5 + j);
                acc[5][0] = fma4(pe.x, ya0, acc[5][0]); acc[5][1] = fma4(pe.x, ya1, acc[5][1]);
                acc[5][0] = fma4(pe.y, yb0, acc[5][0]); acc[5][1] = fma4(pe.y, yb1, acc[5][1]);
                if (has6) {
                    pe = *(const float2*)(e6 + j);
                    acc[6][0] = fma4(pe.x, ya0, acc[6][0]); acc[6][1] = fma4(pe.x, ya1, acc[6][1]);
                    acc[6][0] = fma4(pe.y, yb0, acc[6][0]); acc[6][1] = fma4(pe.y, yb1, acc[6][1]);
                }
            }
        }

        // noise slab must be in SMEM now; also fences agg h-reads before h writes
        asm volatile("cp.async.wait_group 0;" ::: "memory");
        __syncthreads();

        // star cached in registers (old star)
        const float4* s4 = (const float4*)star;
        float4 s0 = s4[2 * lane], s1 = s4[2 * lane + 1];

        // ---- stage A: sim + noise-norm reductions, q-pairs interleaved ----
        float alpha[7], nscale[7];
#pragma unroll
        for (int q0 = 0; q0 < 7; q0 += 2) {
            const int r0 = w + 8 * q0;
            const int r1 = r0 + 8;
            const bool v0 = (r0 < N_);
            const bool v1 = (q0 + 1 < 7) && (r1 < N_);
            float pa = 0.f, pb = 0.f, pc = 0.f, pd = 0.f;
            if (v0) {
                pa = dot4(acc[q0][0], s0) + dot4(acc[q0][1], s1);
                const float4* m4 = (const float4*)(hN + r0 * D_);
                float4 m0 = m4[2 * lane], m1 = m4[2 * lane + 1];
                pb = dot4(m0, m0) + dot4(m1, m1);
            }
            if (v1) {
                pc = dot4(acc[q0 + 1][0], s0) + dot4(acc[q0 + 1][1], s1);
                const float4* m4 = (const float4*)(hN + r1 * D_);
                float4 m0 = m4[2 * lane], m1 = m4[2 * lane + 1];
                pd = dot4(m0, m0) + dot4(m1, m1);
            }
#pragma unroll
            for (int o = 16; o; o >>= 1) {
                pa += sx(pa, o);
                pb += sx(pb, o);
                pc += sx(pc, o);
                pd += sx(pd, o);
            }
            alpha[q0]  = 1.f / (1.f + __expf(-pa * 0.0625f));
            nscale[q0] = 0.4f / fmaxf(sqrtf(pb), 1e-12f);
            if (q0 + 1 < 7) {
                alpha[q0 + 1]  = 1.f / (1.f + __expf(-pc * 0.0625f));
                nscale[q0 + 1] = 0.4f / fmaxf(sqrtf(pd), 1e-12f);
            }
        }

        // ---- stage B: mix + signed noise (no reductions) ----
        float pd1[7];
#pragma unroll
        for (int q = 0; q < 7; q++) {
            const int r = w + 8 * q;
            pd1[q] = 0.f;
            if (r < N_) {
                const float al = alpha[q], om = 1.f - al, sc = nscale[q];
                const float4* m4 = (const float4*)(hN + r * D_);
                float4 n0 = m4[2 * lane], n1 = m4[2 * lane + 1];
                float4 v0, v1;
                v0.x = om * acc[q][0].x + al * s0.x;
                v0.y = om * acc[q][0].y + al * s0.y;
                v0.z = om * acc[q][0].z + al * s0.z;
                v0.w = om * acc[q][0].w + al * s0.w;
                v1.x = om * acc[q][1].x + al * s1.x;
                v1.y = om * acc[q][1].y + al * s1.y;
                v1.z = om * acc[q][1].z + al * s1.z;
                v1.w = om * acc[q][1].w + al * s1.w;
                v0.x = fmaf(sgnf(v0.x) * sc, n0.x, v0.x);
                v0.y = fmaf(sgnf(v0.y) * sc, n0.y, v0.y);
                v0.z = fmaf(sgnf(v0.z) * sc, n0.z, v0.z);
                v0.w = fmaf(sgnf(v0.w) * sc, n0.w, v0.w);
                v1.x = fmaf(sgnf(v1.x) * sc, n1.x, v1.x);
                v1.y = fmaf(sgnf(v1.y) * sc, n1.y, v1.y);
                v1.z = fmaf(sgnf(v1.z) * sc, n1.z, v1.z);
                v1.w = fmaf(sgnf(v1.w) * sc, n1.w, v1.w);
                acc[q][0] = v0;
                acc[q][1] = v1;
                pd1[q] = dot4(v0, s0) + dot4(v1, s1);  // att_pool numerator
            }
        }

        // ---- stage C: all 7 d1 chains in one interleaved butterfly ----
#pragma unroll
        for (int o = 16; o; o >>= 1) {
#pragma unroll
            for (int q = 0; q < 7; q++)
                pd1[q] += sx(pd1[q], o);
        }
        if (lane == 0) {
#pragma unroll
            for (int q = 0; q < 7; q++) {
                const int r = w + 8 * q;
                if (r < N_) simb[r] = __expf(pd1[q]) * gmF[r];
            }
        }

        // ---- write new h + accumulate hg ----
#pragma unroll
        for (int q = 0; q < 7; q++) {
            const int r = w + 8 * q;
            if (r < N_) {
                float4* h4 = (float4*)(h + r * D_);
                h4[2 * lane] = acc[q][0];
                h4[2 * lane + 1] = acc[q][1];
                float4* g4 = (float4*)(g_hg + bo + (size_t)r * D_);
                if (st == 0) {
                    g4[2 * lane] = acc[q][0];
                    g4[2 * lane + 1] = acc[q][1];
                } else {
                    float4 t0 = g4[2 * lane], t1 = g4[2 * lane + 1];
                    t0.x += acc[q][0].x; t0.y += acc[q][0].y;
                    t0.z += acc[q][0].z; t0.w += acc[q][0].w;
                    t1.x += acc[q][1].x; t1.y += acc[q][1].y;
                    t1.z += acc[q][1].z; t1.w += acc[q][1].w;
                    g4[2 * lane] = t0;
                    g4[2 * lane + 1] = t1;
                }
            }
        }
        __syncthreads();

        // ---- star = att_pool weighted sum ----
        {
            float S = 0.f;
            for (int n = 0; n < N_; n++) S += simb[n];
            float inv = 1.f / (S + 1e-24f);
            float s = 0.f;
            for (int n = 0; n < N_; n++) s = fmaf(simb[n], h[n * D_ + tid], s);
            __syncthreads();          // everyone done reading old star
            star[tid] = s * inv;
        }
        __syncthreads();
    }

    // ---- outputs: star ----
    ostar[b * D_ + tid] = star[tid];

    // regather h0 into hN (h holds final hidden hL)
    for (int idx = tid; idx < N_ * D_; idx += 256) {
        int n = idx >> 8;
        hN[idx] = emb[(size_t)nid[n] * D_ + (idx & 255)];
    }
    __syncthreads();

    const int o = tid;  // output column, 0..255
    const float bA = bhn[o];
    const float bB = bhn1[o];

    // ===== gate A in 4 row-chunks (peak acc regs 26 vs 100) =====
    gate_chunk_A<13>(0,  hN, h, Whn, bA, out0, out1, bo, o);
    gate_chunk_A<13>(13, hN, h, Whn, bA, out0, out1, bo, o);
    gate_chunk_A<12>(26, hN, h, Whn, bA, out0, out1, bo, o);
    gate_chunk_A<12>(38, hN, h, Whn, bA, out0, out1, bo, o);
    __syncthreads();

    // overwrite hL region with hg1 = hg_sum / 3
    for (int idx = tid; idx < N_ * D_; idx += 256)
        h[idx] = g_hg[bo + idx] * (1.f / 3.f);
    __syncthreads();

    // ===== gate B in 4 row-chunks =====
    gate_chunk_B<13>(0,  hN, h, Whn1, bB, out1, bo, o);
    gate_chunk_B<13>(13, hN, h, Whn1, bB, out1, bo, o);
    gate_chunk_B<12>(26, hN, h, Whn1, bB, out1, bo, o);
    gate_chunk_B<12>(38, hN, h, Whn1, bB, out1, bo, o);
}

// ---------------- launch ----------------
extern "C" void kernel_launch(void* const* d_in, const int* in_sizes, int n_in,
                              void* d_out, int out_size) {
    (void)in_sizes; (void)n_in; (void)out_size;
    const int*   inputs = (const int*)d_in[0];
    const int*   Am     = (const int*)d_in[1];
    const int*   gmask  = (const int*)d_in[2];
    /* d_in[3] = item (unused by reference) */
    const float* noise  = (const float*)d_in[4];
    const float* emb    = (const float*)d_in[5];
    const float* a0     = (const float*)d_in[6];
    const float* a1     = (const float*)d_in[7];
    const float* a2     = (const float*)d_in[8];
    const float* a3     = (const float*)d_in[9];
    const float* Whn    = (const float*)d_in[10];
    const float* bhn    = (const float*)d_in[11];
    const float* Whn1   = (const float*)d_in[12];
    const float* bhn1   = (const float*)d_in[13];

    float* out  = (float*)d_out;
    float* out0 = out;                                 // [B,N,D]
    float* ostar = out + (size_t)B_ * N_ * D_;         // [B,D]
    float* out1 = ostar + (size_t)B_ * D_;             // [B,N,D]

    cudaFuncSetAttribute(sg_kernel, cudaFuncAttributeMaxDynamicSharedMemorySize,
                         SMEM_BYTES);
    sg_kernel<<<B_, 256, SMEM_BYTES>>>(inputs, Am, gmask, noise, emb,
                                       a0, a1, a2, a3, Whn, bhn, Whn1, bhn1,
                                       out0, ostar, out1);
}